// round 16
// baseline (speedup 1.0000x reference)
#include <cuda_runtime.h>
#include <cuda_bf16.h>
#include <cuda_fp16.h>
#include <cstdint>
#include <math.h>

#define CD    2048
#define NCOL  512
#define HWD   256
#define HD    256
#define HID   512
#define EPSV  1e-5f

typedef __nv_bfloat16 bf16;
typedef __half hf;

// ---------------- device scratch ----------------
__device__ bf16  g_xth [NCOL * CD];            // BN1 out transposed, bf16 hi/lo (q,k path)
__device__ bf16  g_xtl [NCOL * CD];
__device__ hf    g_xf  [NCOL * CD];            // BN1 out transposed, fp16 single (v path)
__device__ bf16  g_wh  [2 * CD * CD];          // Wq|Wk hi (bf16 3-product)
__device__ bf16  g_wl  [2 * CD * CD];
__device__ hf    g_wvf [CD * CD];              // Wv fp16 single
__device__ hf    g_w1f [HID * CD];             // W1 fp16 single
__device__ hf    g_w2f [CD * HID];             // W2 fp16 single
// attention operands
__device__ bf16  g_qt_h[2 * 8 * 256 * 256];    // [b,head][pos][hd]
__device__ bf16  g_qt_l[2 * 8 * 256 * 256];
__device__ bf16  g_kt_h[2 * 8 * 256 * 256];
__device__ bf16  g_kt_l[2 * 8 * 256 * 256];
__device__ hf    g_vf  [CD * NCOL];            // V fp16 single [channel][col]
__device__ float g_ao  [CD * NCOL];
__device__ float g_x1  [CD * NCOL];
__device__ hf    g_x2f [NCOL * CD];            // BN2 out transposed fp16 single
__device__ hf    g_hf  [NCOL * HID];           // MLP hidden transposed fp16 single

// log key multiplicity (separable reflect-pad collapse)
__constant__ float c_lw[16] = {
    1.6094379124341003f, 2.3025850929940460f, 2.3025850929940460f, 2.3025850929940460f,
    2.1972245773362196f, 2.0794415416798357f, 2.0794415416798357f, 2.0794415416798357f,
    2.0794415416798357f, 2.0794415416798357f, 2.0794415416798357f, 2.1972245773362196f,
    2.3025850929940460f, 2.3025850929940460f, 2.3025850929940460f, 1.6094379124341003f
};

// ---------------- PTX helpers (sm_80-compatible only) ----------------
__device__ __forceinline__ uint32_t smem_u32(const void* p) {
    uint32_t a;
    asm("{ .reg .u64 t; cvta.to.shared.u64 t, %1; cvt.u32.u64 %0, t; }" : "=r"(a) : "l"(p));
    return a;
}
__device__ __forceinline__ void cp_async16(uint32_t sdst, const void* gsrc) {
    asm volatile("cp.async.cg.shared.global [%0], [%1], 16;" :: "r"(sdst), "l"(gsrc));
}
__device__ __forceinline__ void cp_commit() { asm volatile("cp.async.commit_group;"); }
__device__ __forceinline__ void cp_wait1()  { asm volatile("cp.async.wait_group 1;" ::: "memory"); }

#define LDSM4(r, addr) \
    asm volatile("ldmatrix.sync.aligned.m8n8.x4.shared.b16 {%0,%1,%2,%3}, [%4];" \
        : "=r"((r)[0]), "=r"((r)[1]), "=r"((r)[2]), "=r"((r)[3]) : "r"(addr))

#define MMA16816(d, a, b) \
    asm volatile("mma.sync.aligned.m16n8k16.row.col.f32.bf16.bf16.f32 " \
        "{%0,%1,%2,%3},{%4,%5,%6,%7},{%8,%9},{%0,%1,%2,%3};" \
        : "+f"((d)[0]), "+f"((d)[1]), "+f"((d)[2]), "+f"((d)[3]) \
        : "r"((a)[0]), "r"((a)[1]), "r"((a)[2]), "r"((a)[3]), "r"((b)[0]), "r"((b)[1]))

#define MMAH16816(d, a, b) \
    asm volatile("mma.sync.aligned.m16n8k16.row.col.f32.f16.f16.f32 " \
        "{%0,%1,%2,%3},{%4,%5,%6,%7},{%8,%9},{%0,%1,%2,%3};" \
        : "+f"((d)[0]), "+f"((d)[1]), "+f"((d)[2]), "+f"((d)[3]) \
        : "r"((a)[0]), "r"((a)[1]), "r"((a)[2]), "r"((a)[3]), "r"((b)[0]), "r"((b)[1]))

__device__ __forceinline__ uint32_t pack_bf16(bf16 a, bf16 b) {
    return (uint32_t)__bfloat16_as_ushort(a) | ((uint32_t)__bfloat16_as_ushort(b) << 16);
}
__device__ __forceinline__ uint32_t pack_hf(hf a, hf b) {
    return (uint32_t)__half_as_ushort(a) | ((uint32_t)__half_as_ushort(b) << 16);
}

// ---------------- BN1 + transpose: bf16 hi/lo (qk) + fp16 single (v) ----------------
__global__ void bn1_t_kernel(const float* __restrict__ x,
                             const float* __restrict__ g, const float* __restrict__ b,
                             const float* __restrict__ m, const float* __restrict__ v)
{
    __shared__ float t[32][33];
    int c0 = blockIdx.x * 32, hw0 = blockIdx.y * 32, bb = blockIdx.z;
    int tx = threadIdx.x, ty = threadIdx.y;
#pragma unroll
    for (int i = 0; i < 4; i++) {
        int c = c0 + ty + i * 8;
        float s  = g[c] * rsqrtf(v[c] + EPSV);
        float sh = b[c] - m[c] * s;
        t[ty + i * 8][tx] = x[((size_t)bb * CD + c) * HWD + hw0 + tx] * s + sh;
    }
    __syncthreads();
#pragma unroll
    for (int i = 0; i < 4; i++) {
        float val = t[tx][ty + i * 8];
        int n = bb * HWD + hw0 + ty + i * 8;
        size_t di = (size_t)n * CD + c0 + tx;
        bf16 h = __float2bfloat16_rn(val);
        g_xth[di] = h;
        g_xtl[di] = __float2bfloat16_rn(val - __bfloat162float(h));
        g_xf[di]  = __float2half_rn(val);
    }
}

// ---------------- weight splits ----------------
__device__ __forceinline__ void split4_bf(const float* __restrict__ src, bf16* __restrict__ dh,
                                          bf16* __restrict__ dl, int i)
{
    float4 v = ((const float4*)src)[i];
    bf16 h0 = __float2bfloat16_rn(v.x), h1 = __float2bfloat16_rn(v.y);
    bf16 h2 = __float2bfloat16_rn(v.z), h3 = __float2bfloat16_rn(v.w);
    bf16 l0 = __float2bfloat16_rn(v.x - __bfloat162float(h0));
    bf16 l1 = __float2bfloat16_rn(v.y - __bfloat162float(h1));
    bf16 l2 = __float2bfloat16_rn(v.z - __bfloat162float(h2));
    bf16 l3 = __float2bfloat16_rn(v.w - __bfloat162float(h3));
    uint2 ph, pl;
    ph.x = pack_bf16(h0, h1); ph.y = pack_bf16(h2, h3);
    pl.x = pack_bf16(l0, l1); pl.y = pack_bf16(l2, l3);
    ((uint2*)dh)[i] = ph;
    ((uint2*)dl)[i] = pl;
}
__device__ __forceinline__ void conv4_hf(const float* __restrict__ src, hf* __restrict__ d, int i)
{
    float4 v = ((const float4*)src)[i];
    uint2 p;
    p.x = pack_hf(__float2half_rn(v.x), __float2half_rn(v.y));
    p.y = pack_hf(__float2half_rn(v.z), __float2half_rn(v.w));
    ((uint2*)d)[i] = p;
}

// Wq, Wk -> bf16 hi/lo
__global__ void wsplit_qk_kernel(const float* __restrict__ a, const float* __restrict__ b)
{
    const int n4 = CD * CD / 4;
    int w = blockIdx.y;
    const float* src = (w == 0) ? a : b;
    bf16* dh = g_wh + (size_t)w * CD * CD;
    bf16* dl = g_wl + (size_t)w * CD * CD;
    int stride = gridDim.x * blockDim.x;
    for (int i = blockIdx.x * blockDim.x + threadIdx.x; i < n4; i += stride)
        split4_bf(src, dh, dl, i);
}
// Wv, W1, W2 -> fp16 single
__global__ void wsplit_f_kernel(const float* __restrict__ a, const float* __restrict__ b,
                                const float* __restrict__ c)
{
    int w = blockIdx.y;
    const float* src = (w == 0) ? a : (w == 1) ? b : c;
    hf* d = (w == 0) ? g_wvf : (w == 1) ? g_w1f : g_w2f;
    int n4 = (w == 0) ? CD * CD / 4 : HID * CD / 4;
    int stride = gridDim.x * blockDim.x;
    for (int i = blockIdx.x * blockDim.x + threadIdx.x; i < n4; i += stride)
        conv4_hf(src, d, i);
}

// ---------------- gemm3: bf16 3-product, q/k epilogue (transpose + bf16 hi/lo) ----------------
__global__ void __launch_bounds__(128, 5) gemm3_qk(
    const bf16* __restrict__ Ah, const bf16* __restrict__ Al,
    const bf16* __restrict__ Bh, const bf16* __restrict__ Bl,
    const float* __restrict__ bq, const float* __restrict__ bk, int K)
{
    constexpr int BM = 64, BN = 64;
    constexpr int OBYT = 64 * 80;
    constexpr int CHB  = 4 * OBYT;
    constexpr int NI = 4;

    extern __shared__ __align__(16) char dsm[];
    const uint32_t sbase = smem_u32(dsm);

    const int tid  = threadIdx.x;
    const int wid  = tid >> 5;
    const int lane = tid & 31;
    const int wm   = wid & 1;
    const int wn   = wid >> 1;
    const int m0   = blockIdx.x * BM;
    const int n0   = blockIdx.y * BN;

    const bf16* pAh = Ah + (size_t)m0 * K;
    const bf16* pAl = Al + (size_t)m0 * K;
    const bf16* pBh = Bh + (size_t)n0 * K;
    const bf16* pBl = Bl + (size_t)n0 * K;

    float acc[2][NI][4];
#pragma unroll
    for (int mi = 0; mi < 2; mi++)
#pragma unroll
        for (int ni = 0; ni < NI; ni++)
#pragma unroll
            for (int j = 0; j < 4; j++) acc[mi][ni][j] = 0.f;

    const int nch = K >> 5;

    auto load_chunk = [&](int slot, int ko) {
        const uint32_t st = sbase + slot * CHB;
        for (int i = tid; i < 256; i += 128) {
            int row = i >> 2, seg = i & 3;
            uint32_t off = row * 80 + seg * 16;
            size_t   gof = (size_t)row * K + ko + seg * 8;
            cp_async16(st + off,            pAh + gof);
            cp_async16(st + OBYT + off,     pAl + gof);
            cp_async16(st + 2 * OBYT + off, pBh + gof);
            cp_async16(st + 3 * OBYT + off, pBl + gof);
        }
    };

    load_chunk(0, 0); cp_commit();

    const int lrow = (lane & 7) + ((lane >> 3) & 1) * 8;
    const int lcol = (lane >> 4) * 8;

    for (int ch = 0; ch < nch; ch++) {
        if (ch + 1 < nch) load_chunk((ch + 1) & 1, (ch + 1) * 32);
        cp_commit();
        cp_wait1();
        __syncthreads();
        const uint32_t st = sbase + (ch & 1) * CHB;

#pragma unroll
        for (int ks = 0; ks < 32; ks += 16) {
            uint32_t ah[2][4], al[2][4];
#pragma unroll
            for (int mi = 0; mi < 2; mi++) {
                uint32_t addr = st + (wm * 32 + mi * 16 + lrow) * 80 + (ks + lcol) * 2;
                LDSM4(ah[mi], addr);
                LDSM4(al[mi], addr + OBYT);
            }
            uint32_t bh[NI][2], bl[NI][2];
#pragma unroll
            for (int np = 0; np < NI / 2; np++) {
                uint32_t addr = st + 2 * OBYT + (wn * 32 + np * 16 + lrow) * 80 + (ks + lcol) * 2;
                uint32_t r[4];
                LDSM4(r, addr);
                bh[2 * np][0] = r[0]; bh[2 * np][1] = r[2];
                bh[2 * np + 1][0] = r[1]; bh[2 * np + 1][1] = r[3];
                LDSM4(r, addr + OBYT);
                bl[2 * np][0] = r[0]; bl[2 * np][1] = r[2];
                bl[2 * np + 1][0] = r[1]; bl[2 * np + 1][1] = r[3];
            }
#pragma unroll
            for (int mi = 0; mi < 2; mi++)
#pragma unroll
                for (int ni = 0; ni < NI; ni++) MMA16816(acc[mi][ni], ah[mi], bh[ni]);
#pragma unroll
            for (int mi = 0; mi < 2; mi++)
#pragma unroll
                for (int ni = 0; ni < NI; ni++) MMA16816(acc[mi][ni], ah[mi], bl[ni]);
#pragma unroll
            for (int mi = 0; mi < 2; mi++)
#pragma unroll
                for (int ni = 0; ni < NI; ni++) MMA16816(acc[mi][ni], al[mi], bh[ni]);
        }
        __syncthreads();
    }

    // epilogue: transpose + bf16 hi/lo -> g_qt / g_kt
    const int seg  = m0 >> 11;          // 0=q, 1=k
    const int mloc = m0 & 2047;
    const float* bp = (seg == 0) ? bq : bk;
    bf16* sh_ = (bf16*)dsm;
    bf16* sl_ = (bf16*)(dsm + BM * BN * 2);
    __syncthreads();
#pragma unroll
    for (int mi = 0; mi < 2; mi++) {
        int rl = wm * 32 + mi * 16 + (lane >> 2);
        float bv0 = bp[mloc + rl], bv1 = bp[mloc + rl + 8];
#pragma unroll
        for (int ni = 0; ni < NI; ni++) {
            int cl = wn * 32 + ni * 8 + (lane & 3) * 2;
            float* a = acc[mi][ni];
            float v00 = a[0] + bv0, v01 = a[1] + bv0;
            float v10 = a[2] + bv1, v11 = a[3] + bv1;
            bf16 h;
            h = __float2bfloat16_rn(v00); sh_[(cl)     * BM + rl]     = h;
            sl_[(cl)     * BM + rl]     = __float2bfloat16_rn(v00 - __bfloat162float(h));
            h = __float2bfloat16_rn(v01); sh_[(cl + 1) * BM + rl]     = h;
            sl_[(cl + 1) * BM + rl]     = __float2bfloat16_rn(v01 - __bfloat162float(h));
            h = __float2bfloat16_rn(v10); sh_[(cl)     * BM + rl + 8] = h;
            sl_[(cl)     * BM + rl + 8] = __float2bfloat16_rn(v10 - __bfloat162float(h));
            h = __float2bfloat16_rn(v11); sh_[(cl + 1) * BM + rl + 8] = h;
            sl_[(cl + 1) * BM + rl + 8] = __float2bfloat16_rn(v11 - __bfloat162float(h));
        }
    }
    __syncthreads();
    bf16* dh = (seg == 0) ? g_qt_h : g_kt_h;
    bf16* dl = (seg == 0) ? g_qt_l : g_kt_l;
    const int head = mloc >> 8, hd0 = mloc & 255;
    for (int i = tid; i < 64 * 8; i += 128) {
        int row = i >> 3, part = i & 7;
        int nn = n0 + row, bb = nn >> 8, pos = nn & 255;
        size_t di = ((size_t)((bb * 8 + head) * 256 + pos)) * 256 + hd0 + part * 8;
        *(uint4*)(dh + di) = *(const uint4*)((const char*)sh_ + row * 128 + part * 16);
        *(uint4*)(dl + di) = *(const uint4*)((const char*)sl_ + row * 128 + part * 16);
    }
}

// ---------------- gemm1: plain fp16 single-product GEMM ----------------
// EPI 0: V — +bias -> fp16 single g_vf [channel][NCOL]
// EPI 1: MLP1 — ReLU6(+bias) -> transposed fp16 single g_hf
// EPI 2: MLP2 — +bias +res -> (B,C,HW) fp32
template <int EPI>
__global__ void __launch_bounds__(128, 6) gemm1_hf(
    const hf* __restrict__ A, const hf* __restrict__ B,
    const float* __restrict__ bias, float* __restrict__ Y,
    const float* __restrict__ res, int K)
{
    constexpr int BM = 64, BN = 64;
    constexpr int OBYT = 64 * 80;           // 5120
    constexpr int CHB  = 2 * OBYT;          // 10240
    constexpr int NI = 4;

    extern __shared__ __align__(16) char dsm[];
    const uint32_t sbase = smem_u32(dsm);

    const int tid  = threadIdx.x;
    const int wid  = tid >> 5;
    const int lane = tid & 31;
    const int wm   = wid & 1;
    const int wn   = wid >> 1;
    const int m0   = blockIdx.x * BM;
    const int n0   = blockIdx.y * BN;

    const hf* pA = A + (size_t)m0 * K;
    const hf* pB = B + (size_t)n0 * K;

    float acc[2][NI][4];
#pragma unroll
    for (int mi = 0; mi < 2; mi++)
#pragma unroll
        for (int ni = 0; ni < NI; ni++)
#pragma unroll
            for (int j = 0; j < 4; j++) acc[mi][ni][j] = 0.f;

    const int nch = K >> 5;

    auto load_chunk = [&](int slot, int ko) {
        const uint32_t st = sbase + slot * CHB;
        for (int i = tid; i < 256; i += 128) {
            int row = i >> 2, seg = i & 3;
            uint32_t off = row * 80 + seg * 16;
            size_t   gof = (size_t)row * K + ko + seg * 8;
            cp_async16(st + off,        pA + gof);
            cp_async16(st + OBYT + off, pB + gof);
        }
    };

    load_chunk(0, 0); cp_commit();

    const int lrow = (lane & 7) + ((lane >> 3) & 1) * 8;
    const int lcol = (lane >> 4) * 8;

    for (int ch = 0; ch < nch; ch++) {
        if (ch + 1 < nch) load_chunk((ch + 1) & 1, (ch + 1) * 32);
        cp_commit();
        cp_wait1();
        __syncthreads();
        const uint32_t st = sbase + (ch & 1) * CHB;

#pragma unroll
        for (int ks = 0; ks < 32; ks += 16) {
            uint32_t a_[2][4];
#pragma unroll
            for (int mi = 0; mi < 2; mi++) {
                uint32_t addr = st + (wm * 32 + mi * 16 + lrow) * 80 + (ks + lcol) * 2;
                LDSM4(a_[mi], addr);
            }
            uint32_t b_[NI][2];
#pragma unroll
            for (int np = 0; np < NI / 2; np++) {
                uint32_t addr = st + OBYT + (wn * 32 + np * 16 + lrow) * 80 + (ks + lcol) * 2;
                uint32_t r[4];
                LDSM4(r, addr);
                b_[2 * np][0] = r[0]; b_[2 * np][1] = r[2];
                b_[2 * np + 1][0] = r[1]; b_[2 * np + 1][1] = r[3];
            }
#pragma unroll
            for (int mi = 0; mi < 2; mi++)
#pragma unroll
                for (int ni = 0; ni < NI; ni++) MMAH16816(acc[mi][ni], a_[mi], b_[ni]);
        }
        __syncthreads();
    }

    // ---- epilogues ----
    if (EPI == 0) {
        // V: fp16 single [channel][NCOL]
#pragma unroll
        for (int mi = 0; mi < 2; mi++) {
            int r0 = m0 + wm * 32 + mi * 16 + (lane >> 2);
            float bv0 = bias[r0], bv1 = bias[r0 + 8];
#pragma unroll
            for (int ni = 0; ni < NI; ni++) {
                int c = n0 + wn * 32 + ni * 8 + (lane & 3) * 2;
                float* a = acc[mi][ni];
                *(uint32_t*)&g_vf[(size_t)r0 * NCOL + c] =
                    pack_hf(__float2half_rn(a[0] + bv0), __float2half_rn(a[1] + bv0));
                *(uint32_t*)&g_vf[(size_t)(r0 + 8) * NCOL + c] =
                    pack_hf(__float2half_rn(a[2] + bv1), __float2half_rn(a[3] + bv1));
            }
        }
        return;
    }

    if (EPI == 1) {
        hf* sh_ = (hf*)dsm;       // [64 n][64 m] fp16
        __syncthreads();
#pragma unroll
        for (int mi = 0; mi < 2; mi++) {
            int rl = wm * 32 + mi * 16 + (lane >> 2);
            float bv0 = bias[m0 + rl], bv1 = bias[m0 + rl + 8];
#pragma unroll
            for (int ni = 0; ni < NI; ni++) {
                int cl = wn * 32 + ni * 8 + (lane & 3) * 2;
                float* a = acc[mi][ni];
                sh_[(cl)     * BM + rl]     = __float2half_rn(fminf(fmaxf(a[0] + bv0, 0.f), 6.f));
                sh_[(cl + 1) * BM + rl]     = __float2half_rn(fminf(fmaxf(a[1] + bv0, 0.f), 6.f));
                sh_[(cl)     * BM + rl + 8] = __float2half_rn(fminf(fmaxf(a[2] + bv1, 0.f), 6.f));
                sh_[(cl + 1) * BM + rl + 8] = __float2half_rn(fminf(fmaxf(a[3] + bv1, 0.f), 6.f));
            }
        }
        __syncthreads();
        for (int i = tid; i < 64 * 8; i += 128) {
            int row = i >> 3, part = i & 7;
            int n = n0 + row;
            *(uint4*)(g_hf + (size_t)n * HID + m0 + part * 8) =
                *(const uint4*)((const char*)sh_ + row * 128 + part * 16);
        }
        return;
    }

    // EPI 2
#pragma unroll
    for (int mi = 0; mi < 2; mi++) {
        int r0 = m0 + wm * 32 + mi * 16 + (lane >> 2);
        float bv0 = bias[r0], bv1 = bias[r0 + 8];
#pragma unroll
        for (int ni = 0; ni < NI; ni++) {
            int c = n0 + wn * 32 + ni * 8 + (lane & 3) * 2;
            float* a = acc[mi][ni];
            int bb = c >> 8, hw = c & 255;
            const float* rp0 = res + (size_t)r0 * NCOL + c;
            const float* rp1 = res + (size_t)(r0 + 8) * NCOL + c;
            float2 v0 = make_float2(a[0] + bv0 + rp0[0], a[1] + bv0 + rp0[1]);
            float2 v1 = make_float2(a[2] + bv1 + rp1[0], a[3] + bv1 + rp1[1]);
            *(float2*)(Y + ((size_t)bb * CD + r0) * HWD + hw) = v0;
            *(float2*)(Y + ((size_t)bb * CD + r0 + 8) * HWD + hw) = v1;
        }
    }
}

// ---------------- tensor-core attention (collapsed keys + log-W bias) ----------------
// phase1: bf16 3-product QK^T; phase2: fp16 single P x single V (1 product)
#define ATT_E    0
#define ATT_P    33792
#define ATT_QH   (ATT_P + 16896)
#define ATT_QL   (ATT_QH + 16896)
#define ATT_RING (ATT_QL + 16896)
#define ATT_SMEM (ATT_RING + 2 * 40960)   // 166400

__global__ void __launch_bounds__(256) attn_kernel()
{
    extern __shared__ __align__(16) char asmem[];
    float* sE = (float*)(asmem + ATT_E);
    const uint32_t sb = smem_u32(asmem);

    const int bn = blockIdx.x;
    const int b  = bn >> 3;
    const int n  = bn & 7;
    const int q0 = blockIdx.y * 32;
    const int tid  = threadIdx.x;
    const int wid  = tid >> 5;
    const int lane = tid & 31;
    const int wq   = wid & 1;
    const int ws   = wid >> 1;
    const int lrow = (lane & 7) + ((lane >> 3) & 1) * 8;
    const int lcol = (lane >> 4) * 8;

    const bf16* qh_g = g_qt_h + ((size_t)((b * 8 + n) * 256 + q0)) * 256;
    const bf16* ql_g = g_qt_l + ((size_t)((b * 8 + n) * 256 + q0)) * 256;
    const bf16* kh_g = g_kt_h + ((size_t)((b * 8 + n) * 256)) * 256;
    const bf16* kl_g = g_kt_l + ((size_t)((b * 8 + n) * 256)) * 256;
    const hf*   vf_g = g_vf + (size_t)(n * 256) * NCOL + b * 256;

    for (int i = tid; i < 32 * 32; i += 256) {
        int row = i >> 5, seg = i & 31;
        cp_async16(sb + ATT_QH + row * 528 + seg * 16, qh_g + (size_t)row * 256 + seg * 8);
        cp_async16(sb + ATT_QL + row * 528 + seg * 16, ql_g + (size_t)row * 256 + seg * 8);
    }
    cp_commit();

    auto load_k = [&](int slot, int ko) {
        const uint32_t st = sb + ATT_RING + slot * 40960;
        for (int i = tid; i < 1024; i += 256) {
            int r = i >> 2, sg = i & 3;
            cp_async16(st + r * 80 + sg * 16,         kh_g + (size_t)r * 256 + ko + sg * 8);
            cp_async16(st + 20480 + r * 80 + sg * 16, kl_g + (size_t)r * 256 + ko + sg * 8);
        }
    };
    load_k(0, 0); cp_commit();

    float acc[8][4];
#pragma unroll
    for (int ni = 0; ni < 8; ni++)
#pragma unroll
        for (int j = 0; j < 4; j++) acc[ni][j] = 0.f;

    for (int ch = 0; ch < 8; ch++) {
        if (ch + 1 < 8) load_k((ch + 1) & 1, (ch + 1) * 32);
        cp_commit();
        cp_wait1();
        __syncthreads();
        const uint32_t st = sb + ATT_RING + (ch & 1) * 40960;
#pragma unroll
        for (int ks = 0; ks < 32; ks += 16) {
            uint32_t ah[4], al[4];
            uint32_t qaddr = sb + ATT_QH + (wq * 16 + lrow) * 528 + (ch * 32 + ks + lcol) * 2;
            LDSM4(ah, qaddr);
            LDSM4(al, qaddr + 16896);
            uint32_t bh[8][2], bl[8][2];
#pragma unroll
            for (int np = 0; np < 4; np++) {
                uint32_t kaddr = st + (ws * 64 + np * 16 + lrow) * 80 + (ks + lcol) * 2;
                uint32_t r[4];
                LDSM4(r, kaddr);
                bh[2 * np][0] = r[0]; bh[2 * np][1] = r[2];
                bh[2 * np + 1][0] = r[1]; bh[2 * np + 1][1] = r[3];
                LDSM4(r, kaddr + 20480);
                bl[2 * np][0] = r[0]; bl[2 * np][1] = r[2];
                bl[2 * np + 1][0] = r[1]; bl[2 * np + 1][1] = r[3];
            }
#pragma unroll
            for (int ni = 0; ni < 8; ni++) MMA16816(acc[ni], ah, bh[ni]);
#pragma unroll
            for (int ni = 0; ni < 8; ni++) MMA16816(acc[ni], ah, bl[ni]);
#pragma unroll
            for (int ni = 0; ni < 8; ni++) MMA16816(acc[ni], al, bh[ni]);
        }
        __syncthreads();
    }

    {
        int qr = wq * 16 + (lane >> 2);
#pragma unroll
        for (int ni = 0; ni < 8; ni++) {
            int s = ws * 64 + ni * 8 + (lane & 3) * 2;
            float lw0 = c_lw[s >> 4] + c_lw[s & 15];
            float lw1 = c_lw[(s + 1) >> 4] + c_lw[(s + 1) & 15];
            sE[qr * 264 + s]           = acc[ni][0] + lw0;
            sE[qr * 264 + s + 1]       = acc[ni][1] + lw1;
            sE[(qr + 8) * 264 + s]     = acc[ni][2] + lw0;
            sE[(qr + 8) * 264 + s + 1] = acc[ni][3] + lw1;
        }
    }
    __syncthreads();

    // softmax + P fp16 single (each warp owns 4 rows)
    {
        hf* Pf = (hf*)(asmem + ATT_P);
        for (int r = wid * 4; r < wid * 4 + 4; r++) {
            float* row = sE + r * 264;
            float mx = -1e30f;
#pragma unroll
            for (int s = lane; s < 256; s += 32) mx = fmaxf(mx, row[s]);
#pragma unroll
            for (int o = 16; o > 0; o >>= 1) mx = fmaxf(mx, __shfl_xor_sync(0xffffffffu, mx, o));
            float sum = 0.f;
#pragma unroll
            for (int s = lane; s < 256; s += 32) {
                float e = __expf(row[s] - mx);
                row[s] = e;
                sum += e;
            }
#pragma unroll
            for (int o = 16; o > 0; o >>= 1) sum += __shfl_xor_sync(0xffffffffu, sum, o);
            float inv = 1.f / sum;
#pragma unroll
            for (int s = lane; s < 256; s += 32)
                Pf[r * 264 + s] = __float2half_rn(row[s] * inv);
        }
    }
    __syncthreads();

    // phase 2: O[32q][256hd] = P (single) x V (single), 1 product
    auto load_v = [&](int slot, int so) {
        const uint32_t st = sb + ATT_RING + slot * 40960;
        for (int i = tid; i < 1024; i += 256) {
            int r = i >> 2, sg = i & 3;
            cp_async16(st + r * 80 + sg * 16, vf_g + (size_t)r * NCOL + so + sg * 8);
        }
    };
    load_v(0, 0); cp_commit();

    float acc2[8][4];
#pragma unroll
    for (int ni = 0; ni < 8; ni++)
#pragma unroll
        for (int j = 0; j < 4; j++) acc2[ni][j] = 0.f;

    for (int ch = 0; ch < 8; ch++) {
        if (ch + 1 < 8) load_v((ch + 1) & 1, (ch + 1) * 32);
        cp_commit();
        cp_wait1();
        __syncthreads();
        const uint32_t st = sb + ATT_RING + (ch & 1) * 40960;
#pragma unroll
        for (int ks = 0; ks < 32; ks += 16) {
            uint32_t pf_[4];
            uint32_t paddr = sb + ATT_P + (wq * 16 + lrow) * 528 + (ch * 32 + ks + lcol) * 2;
            LDSM4(pf_, paddr);
            uint32_t b_[8][2];
#pragma unroll
            for (int np = 0; np < 4; np++) {
                uint32_t vaddr = st + (ws * 64 + np * 16 + lrow) * 80 + (ks + lcol) * 2;
                uint32_t r[4];
                LDSM4(r, vaddr);
                b_[2 * np][0] = r[0]; b_[2 * np][1] = r[2];
                b_[2 * np + 1][0] = r[1]; b_[2 * np + 1][1] = r[3];
            }
#pragma unroll
            for (int ni = 0; ni < 8; ni++) MMAH16816(acc2[ni], pf_, b_[ni]);
        }
        __syncthreads();
    }

    float* sO = sE;
    {
        int qloc = wq * 16 + (lane >> 2);
#pragma unroll
        for (int ni = 0; ni < 8; ni++) {
            int hd = ws * 64 + ni * 8 + (lane & 3) * 2;
            sO[hd * 33 + qloc]           = acc2[ni][0];
            sO[(hd + 1) * 33 + qloc]     = acc2[ni][1];
            sO[hd * 33 + qloc + 8]       = acc2[ni][2];
            sO[(hd + 1) * 33 + qloc + 8] = acc2[ni][3];
        }
    }
    __syncthreads();
    for (int i = tid; i < 8192; i += 256) {
        int r = i >> 5, q = i & 31;
        g_ao[(size_t)(n * 256 + r) * NCOL + b * 256 + q0 + q] = sO[r * 33 + q];
    }
}

// ---------------- combine: x1 = x + BN1(x) + gamma*ao ; BN2 -> transposed fp16 single ----------------
__global__ void combine_t_kernel(const float* __restrict__ x, const float* __restrict__ gamma,
                                 const float* __restrict__ g1, const float* __restrict__ b1p,
                                 const float* __restrict__ m1, const float* __restrict__ v1,
                                 const float* __restrict__ g2, const float* __restrict__ b2,
                                 const float* __restrict__ m2, const float* __restrict__ v2)
{
    __shared__ float t[32][33];
    int c0 = blockIdx.x * 32, col0 = blockIdx.y * 32;
    int tx = threadIdx.x, ty = threadIdx.y;
    int col = col0 + tx;
    int bb = col >> 8, hw = col & 255;
    float gm = gamma[0];
#pragma unroll
    for (int i = 0; i < 4; i++) {
        int c = c0 + ty + i * 8;
        size_t idx = (size_t)c * NCOL + col;
        float s1  = g1[c] * rsqrtf(v1[c] + EPSV);
        float sh1 = b1p[c] - m1[c] * s1;
        float xv  = x[((size_t)bb * CD + c) * HWD + hw];
        float x1  = xv + (xv * s1 + sh1) + gm * g_ao[idx];
        g_x1[idx] = x1;
        float s2 = g2[c] * rsqrtf(v2[c] + EPSV);
        t[ty + i * 8][tx] = x1 * s2 + (b2[c] - m2[c] * s2);
    }
    __syncthreads();
#pragma unroll
    for (int i = 0; i < 4; i++) {
        float val = t[tx][ty + i * 8];
        int n = col0 + ty + i * 8;
        g_x2f[(size_t)n * CD + c0 + tx] = __float2half_rn(val);
    }
}

// ---------------- launch ----------------
extern "C" void kernel_launch(void* const* d_in, const int* in_sizes, int n_in,
                              void* d_out, int out_size)
{
    const float* x     = (const float*)d_in[0];
    const float* bn1_g = (const float*)d_in[1];
    const float* bn1_b = (const float*)d_in[2];
    const float* bn1_m = (const float*)d_in[3];
    const float* bn1_v = (const float*)d_in[4];
    const float* Wq    = (const float*)d_in[5];
    const float* bq    = (const float*)d_in[6];
    const float* Wk    = (const float*)d_in[7];
    const float* bk    = (const float*)d_in[8];
    const float* Wv    = (const float*)d_in[9];
    const float* bv    = (const float*)d_in[10];
    const float* gamma = (const float*)d_in[11];
    const float* bn2_g = (const float*)d_in[12];
    const float* bn2_b = (const float*)d_in[13];
    const float* bn2_m = (const float*)d_in[14];
    const float* bn2_v = (const float*)d_in[15];
    const float* W1    = (const float*)d_in[16];
    const float* b1    = (const float*)d_in[17];
    const float* W2    = (const float*)d_in[18];
    const float* b2    = (const float*)d_in[19];
    float* out = (float*)d_out;

    bf16 *p_wh, *p_wl, *p_xth, *p_xtl;
    hf *p_wvf, *p_w1f, *p_w2f, *p_xf, *p_x2f, *p_hf;
    float *p_x1;
    cudaGetSymbolAddress((void**)&p_wh,  g_wh);
    cudaGetSymbolAddress((void**)&p_wl,  g_wl);
    cudaGetSymbolAddress((void**)&p_wvf, g_wvf);
    cudaGetSymbolAddress((void**)&p_w1f, g_w1f);
    cudaGetSymbolAddress((void**)&p_w2f, g_w2f);
    cudaGetSymbolAddress((void**)&p_xth, g_xth);
    cudaGetSymbolAddress((void**)&p_xtl, g_xtl);
    cudaGetSymbolAddress((void**)&p_xf,  g_xf);
    cudaGetSymbolAddress((void**)&p_x2f, g_x2f);
    cudaGetSymbolAddress((void**)&p_hf,  g_hf);
    cudaGetSymbolAddress((void**)&p_x1,  g_x1);

    constexpr int SMG3 = 2 * 4 * 64 * 80;   // 40960
    constexpr int SMG1 = 2 * 2 * 64 * 80;   // 20480
    cudaFuncSetAttribute(gemm3_qk,    cudaFuncAttributeMaxDynamicSharedMemorySize, SMG3);
    cudaFuncSetAttribute(gemm1_hf<0>, cudaFuncAttributeMaxDynamicSharedMemorySize, SMG1);
    cudaFuncSetAttribute(gemm1_hf<1>, cudaFuncAttributeMaxDynamicSharedMemorySize, SMG1);
    cudaFuncSetAttribute(gemm1_hf<2>, cudaFuncAttributeMaxDynamicSharedMemorySize, SMG1);
    cudaFuncSetAttribute(attn_kernel, cudaFuncAttributeMaxDynamicSharedMemorySize, ATT_SMEM);

    // weight splits + BN1
    wsplit_qk_kernel<<<dim3(1024, 2), 256>>>(Wq, Wk);
    wsplit_f_kernel<<<dim3(1024, 3), 256>>>(Wv, W1, W2);
    bn1_t_kernel<<<dim3(CD / 32, HWD / 32, 2), dim3(32, 8)>>>(x, bn1_g, bn1_b, bn1_m, bn1_v);

    // Q,K projection (bf16 3-product): M = 4096
    gemm3_qk<<<dim3(64, 8), 128, SMG3>>>(p_wh, p_wl, p_xth, p_xtl, bq, bk, CD);

    // V projection (fp16 1-product): M = 2048
    gemm1_hf<0><<<dim3(32, 8), 128, SMG1>>>(p_wvf, p_xf, bv, nullptr, nullptr, CD);

    // tensor-core attention
    attn_kernel<<<dim3(16, 8), 256, ATT_SMEM>>>();

    // residual + BN1-recompute + BN2 (-> fp16 single)
    combine_t_kernel<<<dim3(CD / 32, NCOL / 32), dim3(32, 8)>>>(
        x, gamma, bn1_g, bn1_b, bn1_m, bn1_v, bn2_g, bn2_b, bn2_m, bn2_v);

    // MLP1 (fp16 1-product): ReLU6 -> transposed fp16 single
    gemm1_hf<1><<<dim3(HID / 64, NCOL / 64), 128, SMG1>>>(p_w1f, p_x2f, b1, nullptr, nullptr, CD);

    // MLP2 (fp16 1-product): +residual, NCHW out
    gemm1_hf<2><<<dim3(CD / 64, NCOL / 64), 128, SMG1>>>(p_w2f, p_hf, b2, out, p_x1, HID);
}

// round 17
// speedup vs baseline: 1.1576x; 1.1576x over previous
#include <cuda_runtime.h>
#include <cuda_bf16.h>
#include <cuda_fp16.h>
#include <cstdint>
#include <math.h>

#define CD    2048
#define NCOL  512
#define HWD   256
#define HD    256
#define HID   512
#define EPSV  1e-5f

typedef __nv_bfloat16 bf16;
typedef __half hf;

// ---------------- device scratch ----------------
__device__ hf    g_xf  [NCOL * CD];            // BN1 out transposed, fp16 single (q,k,v)
__device__ hf    g_whf [2 * CD * CD];          // Wq|Wk fp16 hi
__device__ hf    g_wlf [2 * CD * CD];          // Wq|Wk fp16 lo
__device__ hf    g_wvf [CD * CD];              // Wv fp16 single
__device__ hf    g_w1f [HID * CD];             // W1 fp16 single
__device__ hf    g_w2f [CD * HID];             // W2 fp16 single
// attention operands
__device__ bf16  g_qt_h[2 * 8 * 256 * 256];    // [b,head][pos][hd]
__device__ bf16  g_qt_l[2 * 8 * 256 * 256];
__device__ bf16  g_kt_h[2 * 8 * 256 * 256];
__device__ bf16  g_kt_l[2 * 8 * 256 * 256];
__device__ hf    g_vf  [CD * NCOL];            // V fp16 single [channel][col]
__device__ float g_ao  [CD * NCOL];
__device__ float g_x1  [CD * NCOL];
__device__ hf    g_x2f [NCOL * CD];            // BN2 out transposed fp16 single
__device__ hf    g_hf  [NCOL * HID];           // MLP hidden transposed fp16 single

// log key multiplicity (separable reflect-pad collapse)
__constant__ float c_lw[16] = {
    1.6094379124341003f, 2.3025850929940460f, 2.3025850929940460f, 2.3025850929940460f,
    2.1972245773362196f, 2.0794415416798357f, 2.0794415416798357f, 2.0794415416798357f,
    2.0794415416798357f, 2.0794415416798357f, 2.0794415416798357f, 2.1972245773362196f,
    2.3025850929940460f, 2.3025850929940460f, 2.3025850929940460f, 1.6094379124341003f
};

// ---------------- PTX helpers (sm_80-compatible only) ----------------
__device__ __forceinline__ uint32_t smem_u32(const void* p) {
    uint32_t a;
    asm("{ .reg .u64 t; cvta.to.shared.u64 t, %1; cvt.u32.u64 %0, t; }" : "=r"(a) : "l"(p));
    return a;
}
__device__ __forceinline__ void cp_async16(uint32_t sdst, const void* gsrc) {
    asm volatile("cp.async.cg.shared.global [%0], [%1], 16;" :: "r"(sdst), "l"(gsrc));
}
__device__ __forceinline__ void cp_commit() { asm volatile("cp.async.commit_group;"); }
__device__ __forceinline__ void cp_wait1()  { asm volatile("cp.async.wait_group 1;" ::: "memory"); }

#define LDSM4(r, addr) \
    asm volatile("ldmatrix.sync.aligned.m8n8.x4.shared.b16 {%0,%1,%2,%3}, [%4];" \
        : "=r"((r)[0]), "=r"((r)[1]), "=r"((r)[2]), "=r"((r)[3]) : "r"(addr))

#define MMA16816(d, a, b) \
    asm volatile("mma.sync.aligned.m16n8k16.row.col.f32.bf16.bf16.f32 " \
        "{%0,%1,%2,%3},{%4,%5,%6,%7},{%8,%9},{%0,%1,%2,%3};" \
        : "+f"((d)[0]), "+f"((d)[1]), "+f"((d)[2]), "+f"((d)[3]) \
        : "r"((a)[0]), "r"((a)[1]), "r"((a)[2]), "r"((a)[3]), "r"((b)[0]), "r"((b)[1]))

#define MMAH16816(d, a, b) \
    asm volatile("mma.sync.aligned.m16n8k16.row.col.f32.f16.f16.f32 " \
        "{%0,%1,%2,%3},{%4,%5,%6,%7},{%8,%9},{%0,%1,%2,%3};" \
        : "+f"((d)[0]), "+f"((d)[1]), "+f"((d)[2]), "+f"((d)[3]) \
        : "r"((a)[0]), "r"((a)[1]), "r"((a)[2]), "r"((a)[3]), "r"((b)[0]), "r"((b)[1]))

__device__ __forceinline__ uint32_t pack_bf16(bf16 a, bf16 b) {
    return (uint32_t)__bfloat16_as_ushort(a) | ((uint32_t)__bfloat16_as_ushort(b) << 16);
}
__device__ __forceinline__ uint32_t pack_hf(hf a, hf b) {
    return (uint32_t)__half_as_ushort(a) | ((uint32_t)__half_as_ushort(b) << 16);
}

// ---------------- BN1 + transpose -> fp16 single ----------------
__global__ void bn1_t_kernel(const float* __restrict__ x,
                             const float* __restrict__ g, const float* __restrict__ b,
                             const float* __restrict__ m, const float* __restrict__ v)
{
    __shared__ float t[32][33];
    int c0 = blockIdx.x * 32, hw0 = blockIdx.y * 32, bb = blockIdx.z;
    int tx = threadIdx.x, ty = threadIdx.y;
#pragma unroll
    for (int i = 0; i < 4; i++) {
        int c = c0 + ty + i * 8;
        float s  = g[c] * rsqrtf(v[c] + EPSV);
        float sh = b[c] - m[c] * s;
        t[ty + i * 8][tx] = x[((size_t)bb * CD + c) * HWD + hw0 + tx] * s + sh;
    }
    __syncthreads();
#pragma unroll
    for (int i = 0; i < 4; i++) {
        float val = t[tx][ty + i * 8];
        int n = bb * HWD + hw0 + ty + i * 8;
        g_xf[(size_t)n * CD + c0 + tx] = __float2half_rn(val);
    }
}

// ---------------- weight splits ----------------
__device__ __forceinline__ void split4_hf(const float* __restrict__ src, hf* __restrict__ dh,
                                          hf* __restrict__ dl, int i)
{
    float4 v = ((const float4*)src)[i];
    hf h0 = __float2half_rn(v.x), h1 = __float2half_rn(v.y);
    hf h2 = __float2half_rn(v.z), h3 = __float2half_rn(v.w);
    hf l0 = __float2half_rn(v.x - __half2float(h0));
    hf l1 = __float2half_rn(v.y - __half2float(h1));
    hf l2 = __float2half_rn(v.z - __half2float(h2));
    hf l3 = __float2half_rn(v.w - __half2float(h3));
    uint2 ph, pl;
    ph.x = pack_hf(h0, h1); ph.y = pack_hf(h2, h3);
    pl.x = pack_hf(l0, l1); pl.y = pack_hf(l2, l3);
    ((uint2*)dh)[i] = ph;
    ((uint2*)dl)[i] = pl;
}
__device__ __forceinline__ void conv4_hf(const float* __restrict__ src, hf* __restrict__ d, int i)
{
    float4 v = ((const float4*)src)[i];
    uint2 p;
    p.x = pack_hf(__float2half_rn(v.x), __float2half_rn(v.y));
    p.y = pack_hf(__float2half_rn(v.z), __float2half_rn(v.w));
    ((uint2*)d)[i] = p;
}

// Wq, Wk -> fp16 hi/lo
__global__ void wsplit_qk_kernel(const float* __restrict__ a, const float* __restrict__ b)
{
    const int n4 = CD * CD / 4;
    int w = blockIdx.y;
    const float* src = (w == 0) ? a : b;
    hf* dh = g_whf + (size_t)w * CD * CD;
    hf* dl = g_wlf + (size_t)w * CD * CD;
    int stride = gridDim.x * blockDim.x;
    for (int i = blockIdx.x * blockDim.x + threadIdx.x; i < n4; i += stride)
        split4_hf(src, dh, dl, i);
}
// Wv, W1, W2 -> fp16 single
__global__ void wsplit_f_kernel(const float* __restrict__ a, const float* __restrict__ b,
                                const float* __restrict__ c)
{
    int w = blockIdx.y;
    const float* src = (w == 0) ? a : (w == 1) ? b : c;
    hf* d = (w == 0) ? g_wvf : (w == 1) ? g_w1f : g_w2f;
    int n4 = (w == 0) ? CD * CD / 4 : HID * CD / 4;
    int stride = gridDim.x * blockDim.x;
    for (int i = blockIdx.x * blockDim.x + threadIdx.x; i < n4; i += stride)
        conv4_hf(src, d, i);
}

// ---------------- gemm2f_qk: fp16 2-product (W hi/lo, act single), q/k epilogue ----------------
__global__ void __launch_bounds__(128, 5) gemm2f_qk(
    const hf* __restrict__ Ah, const hf* __restrict__ Al, const hf* __restrict__ B,
    const float* __restrict__ bq, const float* __restrict__ bk, int K)
{
    constexpr int BM = 64, BN = 64;
    constexpr int OBYT = 64 * 80;           // 5120
    constexpr int CHB  = 3 * OBYT;          // 15360
    constexpr int NI = 4;

    extern __shared__ __align__(16) char dsm[];
    const uint32_t sbase = smem_u32(dsm);

    const int tid  = threadIdx.x;
    const int wid  = tid >> 5;
    const int lane = tid & 31;
    const int wm   = wid & 1;
    const int wn   = wid >> 1;
    const int m0   = blockIdx.x * BM;
    const int n0   = blockIdx.y * BN;

    const hf* pAh = Ah + (size_t)m0 * K;
    const hf* pAl = Al + (size_t)m0 * K;
    const hf* pB  = B  + (size_t)n0 * K;

    float acc[2][NI][4];
#pragma unroll
    for (int mi = 0; mi < 2; mi++)
#pragma unroll
        for (int ni = 0; ni < NI; ni++)
#pragma unroll
            for (int j = 0; j < 4; j++) acc[mi][ni][j] = 0.f;

    const int nch = K >> 5;

    auto load_chunk = [&](int slot, int ko) {
        const uint32_t st = sbase + slot * CHB;
        for (int i = tid; i < 256; i += 128) {
            int row = i >> 2, seg = i & 3;
            uint32_t off = row * 80 + seg * 16;
            size_t   gof = (size_t)row * K + ko + seg * 8;
            cp_async16(st + off,            pAh + gof);
            cp_async16(st + OBYT + off,     pAl + gof);
            cp_async16(st + 2 * OBYT + off, pB  + gof);
        }
    };

    load_chunk(0, 0); cp_commit();

    const int lrow = (lane & 7) + ((lane >> 3) & 1) * 8;
    const int lcol = (lane >> 4) * 8;

    for (int ch = 0; ch < nch; ch++) {
        if (ch + 1 < nch) load_chunk((ch + 1) & 1, (ch + 1) * 32);
        cp_commit();
        cp_wait1();
        __syncthreads();
        const uint32_t st = sbase + (ch & 1) * CHB;

#pragma unroll
        for (int ks = 0; ks < 32; ks += 16) {
            uint32_t ah[2][4], al[2][4];
#pragma unroll
            for (int mi = 0; mi < 2; mi++) {
                uint32_t addr = st + (wm * 32 + mi * 16 + lrow) * 80 + (ks + lcol) * 2;
                LDSM4(ah[mi], addr);
                LDSM4(al[mi], addr + OBYT);
            }
            uint32_t b_[NI][2];
#pragma unroll
            for (int np = 0; np < NI / 2; np++) {
                uint32_t addr = st + 2 * OBYT + (wn * 32 + np * 16 + lrow) * 80 + (ks + lcol) * 2;
                uint32_t r[4];
                LDSM4(r, addr);
                b_[2 * np][0] = r[0]; b_[2 * np][1] = r[2];
                b_[2 * np + 1][0] = r[1]; b_[2 * np + 1][1] = r[3];
            }
#pragma unroll
            for (int mi = 0; mi < 2; mi++)
#pragma unroll
                for (int ni = 0; ni < NI; ni++) MMAH16816(acc[mi][ni], ah[mi], b_[ni]);
#pragma unroll
            for (int mi = 0; mi < 2; mi++)
#pragma unroll
                for (int ni = 0; ni < NI; ni++) MMAH16816(acc[mi][ni], al[mi], b_[ni]);
        }
        __syncthreads();
    }

    // epilogue: transpose + bf16 hi/lo -> g_qt / g_kt
    const int seg  = m0 >> 11;          // 0=q, 1=k
    const int mloc = m0 & 2047;
    const float* bp = (seg == 0) ? bq : bk;
    bf16* sh_ = (bf16*)dsm;
    bf16* sl_ = (bf16*)(dsm + BM * BN * 2);
    __syncthreads();
#pragma unroll
    for (int mi = 0; mi < 2; mi++) {
        int rl = wm * 32 + mi * 16 + (lane >> 2);
        float bv0 = bp[mloc + rl], bv1 = bp[mloc + rl + 8];
#pragma unroll
        for (int ni = 0; ni < NI; ni++) {
            int cl = wn * 32 + ni * 8 + (lane & 3) * 2;
            float* a = acc[mi][ni];
            float v00 = a[0] + bv0, v01 = a[1] + bv0;
            float v10 = a[2] + bv1, v11 = a[3] + bv1;
            bf16 h;
            h = __float2bfloat16_rn(v00); sh_[(cl)     * BM + rl]     = h;
            sl_[(cl)     * BM + rl]     = __float2bfloat16_rn(v00 - __bfloat162float(h));
            h = __float2bfloat16_rn(v01); sh_[(cl + 1) * BM + rl]     = h;
            sl_[(cl + 1) * BM + rl]     = __float2bfloat16_rn(v01 - __bfloat162float(h));
            h = __float2bfloat16_rn(v10); sh_[(cl)     * BM + rl + 8] = h;
            sl_[(cl)     * BM + rl + 8] = __float2bfloat16_rn(v10 - __bfloat162float(h));
            h = __float2bfloat16_rn(v11); sh_[(cl + 1) * BM + rl + 8] = h;
            sl_[(cl + 1) * BM + rl + 8] = __float2bfloat16_rn(v11 - __bfloat162float(h));
        }
    }
    __syncthreads();
    bf16* dh = (seg == 0) ? g_qt_h : g_kt_h;
    bf16* dl = (seg == 0) ? g_qt_l : g_kt_l;
    const int head = mloc >> 8, hd0 = mloc & 255;
    for (int i = tid; i < 64 * 8; i += 128) {
        int row = i >> 3, part = i & 7;
        int nn = n0 + row, bb = nn >> 8, pos = nn & 255;
        size_t di = ((size_t)((bb * 8 + head) * 256 + pos)) * 256 + hd0 + part * 8;
        *(uint4*)(dh + di) = *(const uint4*)((const char*)sh_ + row * 128 + part * 16);
        *(uint4*)(dl + di) = *(const uint4*)((const char*)sl_ + row * 128 + part * 16);
    }
}

// ---------------- gemm1: plain fp16 single-product GEMM ----------------
// EPI 0: V — +bias -> fp16 single g_vf [channel][NCOL]
// EPI 1: MLP1 — ReLU6(+bias) -> transposed fp16 single g_hf
// EPI 2: MLP2 — +bias +res -> (B,C,HW) fp32
template <int EPI>
__global__ void __launch_bounds__(128, 6) gemm1_hf(
    const hf* __restrict__ A, const hf* __restrict__ B,
    const float* __restrict__ bias, float* __restrict__ Y,
    const float* __restrict__ res, int K)
{
    constexpr int BM = 64, BN = 64;
    constexpr int OBYT = 64 * 80;           // 5120
    constexpr int CHB  = 2 * OBYT;          // 10240
    constexpr int NI = 4;

    extern __shared__ __align__(16) char dsm[];
    const uint32_t sbase = smem_u32(dsm);

    const int tid  = threadIdx.x;
    const int wid  = tid >> 5;
    const int lane = tid & 31;
    const int wm   = wid & 1;
    const int wn   = wid >> 1;
    const int m0   = blockIdx.x * BM;
    const int n0   = blockIdx.y * BN;

    const hf* pA = A + (size_t)m0 * K;
    const hf* pB = B + (size_t)n0 * K;

    float acc[2][NI][4];
#pragma unroll
    for (int mi = 0; mi < 2; mi++)
#pragma unroll
        for (int ni = 0; ni < NI; ni++)
#pragma unroll
            for (int j = 0; j < 4; j++) acc[mi][ni][j] = 0.f;

    const int nch = K >> 5;

    auto load_chunk = [&](int slot, int ko) {
        const uint32_t st = sbase + slot * CHB;
        for (int i = tid; i < 256; i += 128) {
            int row = i >> 2, seg = i & 3;
            uint32_t off = row * 80 + seg * 16;
            size_t   gof = (size_t)row * K + ko + seg * 8;
            cp_async16(st + off,        pA + gof);
            cp_async16(st + OBYT + off, pB + gof);
        }
    };

    load_chunk(0, 0); cp_commit();

    const int lrow = (lane & 7) + ((lane >> 3) & 1) * 8;
    const int lcol = (lane >> 4) * 8;

    for (int ch = 0; ch < nch; ch++) {
        if (ch + 1 < nch) load_chunk((ch + 1) & 1, (ch + 1) * 32);
        cp_commit();
        cp_wait1();
        __syncthreads();
        const uint32_t st = sbase + (ch & 1) * CHB;

#pragma unroll
        for (int ks = 0; ks < 32; ks += 16) {
            uint32_t a_[2][4];
#pragma unroll
            for (int mi = 0; mi < 2; mi++) {
                uint32_t addr = st + (wm * 32 + mi * 16 + lrow) * 80 + (ks + lcol) * 2;
                LDSM4(a_[mi], addr);
            }
            uint32_t b_[NI][2];
#pragma unroll
            for (int np = 0; np < NI / 2; np++) {
                uint32_t addr = st + OBYT + (wn * 32 + np * 16 + lrow) * 80 + (ks + lcol) * 2;
                uint32_t r[4];
                LDSM4(r, addr);
                b_[2 * np][0] = r[0]; b_[2 * np][1] = r[2];
                b_[2 * np + 1][0] = r[1]; b_[2 * np + 1][1] = r[3];
            }
#pragma unroll
            for (int mi = 0; mi < 2; mi++)
#pragma unroll
                for (int ni = 0; ni < NI; ni++) MMAH16816(acc[mi][ni], a_[mi], b_[ni]);
        }
        __syncthreads();
    }

    // ---- epilogues ----
    if (EPI == 0) {
#pragma unroll
        for (int mi = 0; mi < 2; mi++) {
            int r0 = m0 + wm * 32 + mi * 16 + (lane >> 2);
            float bv0 = bias[r0], bv1 = bias[r0 + 8];
#pragma unroll
            for (int ni = 0; ni < NI; ni++) {
                int c = n0 + wn * 32 + ni * 8 + (lane & 3) * 2;
                float* a = acc[mi][ni];
                *(uint32_t*)&g_vf[(size_t)r0 * NCOL + c] =
                    pack_hf(__float2half_rn(a[0] + bv0), __float2half_rn(a[1] + bv0));
                *(uint32_t*)&g_vf[(size_t)(r0 + 8) * NCOL + c] =
                    pack_hf(__float2half_rn(a[2] + bv1), __float2half_rn(a[3] + bv1));
            }
        }
        return;
    }

    if (EPI == 1) {
        hf* sh_ = (hf*)dsm;       // [64 n][64 m] fp16
        __syncthreads();
#pragma unroll
        for (int mi = 0; mi < 2; mi++) {
            int rl = wm * 32 + mi * 16 + (lane >> 2);
            float bv0 = bias[m0 + rl], bv1 = bias[m0 + rl + 8];
#pragma unroll
            for (int ni = 0; ni < NI; ni++) {
                int cl = wn * 32 + ni * 8 + (lane & 3) * 2;
                float* a = acc[mi][ni];
                sh_[(cl)     * BM + rl]     = __float2half_rn(fminf(fmaxf(a[0] + bv0, 0.f), 6.f));
                sh_[(cl + 1) * BM + rl]     = __float2half_rn(fminf(fmaxf(a[1] + bv0, 0.f), 6.f));
                sh_[(cl)     * BM + rl + 8] = __float2half_rn(fminf(fmaxf(a[2] + bv1, 0.f), 6.f));
                sh_[(cl + 1) * BM + rl + 8] = __float2half_rn(fminf(fmaxf(a[3] + bv1, 0.f), 6.f));
            }
        }
        __syncthreads();
        for (int i = tid; i < 64 * 8; i += 128) {
            int row = i >> 3, part = i & 7;
            int n = n0 + row;
            *(uint4*)(g_hf + (size_t)n * HID + m0 + part * 8) =
                *(const uint4*)((const char*)sh_ + row * 128 + part * 16);
        }
        return;
    }

    // EPI 2
#pragma unroll
    for (int mi = 0; mi < 2; mi++) {
        int r0 = m0 + wm * 32 + mi * 16 + (lane >> 2);
        float bv0 = bias[r0], bv1 = bias[r0 + 8];
#pragma unroll
        for (int ni = 0; ni < NI; ni++) {
            int c = n0 + wn * 32 + ni * 8 + (lane & 3) * 2;
            float* a = acc[mi][ni];
            int bb = c >> 8, hw = c & 255;
            const float* rp0 = res + (size_t)r0 * NCOL + c;
            const float* rp1 = res + (size_t)(r0 + 8) * NCOL + c;
            float2 v0 = make_float2(a[0] + bv0 + rp0[0], a[1] + bv0 + rp0[1]);
            float2 v1 = make_float2(a[2] + bv1 + rp1[0], a[3] + bv1 + rp1[1]);
            *(float2*)(Y + ((size_t)bb * CD + r0) * HWD + hw) = v0;
            *(float2*)(Y + ((size_t)bb * CD + r0 + 8) * HWD + hw) = v1;
        }
    }
}

// ---------------- tensor-core attention (collapsed keys + log-W bias) ----------------
// phase1: bf16 3-product QK^T; phase2: fp16 single P x single V (1 product)
#define ATT_E    0
#define ATT_P    33792
#define ATT_QH   (ATT_P + 16896)
#define ATT_QL   (ATT_QH + 16896)
#define ATT_RING (ATT_QL + 16896)
#define ATT_SMEM (ATT_RING + 2 * 40960)   // 166400

__global__ void __launch_bounds__(256) attn_kernel()
{
    extern __shared__ __align__(16) char asmem[];
    float* sE = (float*)(asmem + ATT_E);
    const uint32_t sb = smem_u32(asmem);

    const int bn = blockIdx.x;
    const int b  = bn >> 3;
    const int n  = bn & 7;
    const int q0 = blockIdx.y * 32;
    const int tid  = threadIdx.x;
    const int wid  = tid >> 5;
    const int lane = tid & 31;
    const int wq   = wid & 1;
    const int ws   = wid >> 1;
    const int lrow = (lane & 7) + ((lane >> 3) & 1) * 8;
    const int lcol = (lane >> 4) * 8;

    const bf16* qh_g = g_qt_h + ((size_t)((b * 8 + n) * 256 + q0)) * 256;
    const bf16* ql_g = g_qt_l + ((size_t)((b * 8 + n) * 256 + q0)) * 256;
    const bf16* kh_g = g_kt_h + ((size_t)((b * 8 + n) * 256)) * 256;
    const bf16* kl_g = g_kt_l + ((size_t)((b * 8 + n) * 256)) * 256;
    const hf*   vf_g = g_vf + (size_t)(n * 256) * NCOL + b * 256;

    for (int i = tid; i < 32 * 32; i += 256) {
        int row = i >> 5, seg = i & 31;
        cp_async16(sb + ATT_QH + row * 528 + seg * 16, qh_g + (size_t)row * 256 + seg * 8);
        cp_async16(sb + ATT_QL + row * 528 + seg * 16, ql_g + (size_t)row * 256 + seg * 8);
    }
    cp_commit();

    auto load_k = [&](int slot, int ko) {
        const uint32_t st = sb + ATT_RING + slot * 40960;
        for (int i = tid; i < 1024; i += 256) {
            int r = i >> 2, sg = i & 3;
            cp_async16(st + r * 80 + sg * 16,         kh_g + (size_t)r * 256 + ko + sg * 8);
            cp_async16(st + 20480 + r * 80 + sg * 16, kl_g + (size_t)r * 256 + ko + sg * 8);
        }
    };
    load_k(0, 0); cp_commit();

    float acc[8][4];
#pragma unroll
    for (int ni = 0; ni < 8; ni++)
#pragma unroll
        for (int j = 0; j < 4; j++) acc[ni][j] = 0.f;

    for (int ch = 0; ch < 8; ch++) {
        if (ch + 1 < 8) load_k((ch + 1) & 1, (ch + 1) * 32);
        cp_commit();
        cp_wait1();
        __syncthreads();
        const uint32_t st = sb + ATT_RING + (ch & 1) * 40960;
#pragma unroll
        for (int ks = 0; ks < 32; ks += 16) {
            uint32_t ah[4], al[4];
            uint32_t qaddr = sb + ATT_QH + (wq * 16 + lrow) * 528 + (ch * 32 + ks + lcol) * 2;
            LDSM4(ah, qaddr);
            LDSM4(al, qaddr + 16896);
            uint32_t bh[8][2], bl[8][2];
#pragma unroll
            for (int np = 0; np < 4; np++) {
                uint32_t kaddr = st + (ws * 64 + np * 16 + lrow) * 80 + (ks + lcol) * 2;
                uint32_t r[4];
                LDSM4(r, kaddr);
                bh[2 * np][0] = r[0]; bh[2 * np][1] = r[2];
                bh[2 * np + 1][0] = r[1]; bh[2 * np + 1][1] = r[3];
                LDSM4(r, kaddr + 20480);
                bl[2 * np][0] = r[0]; bl[2 * np][1] = r[2];
                bl[2 * np + 1][0] = r[1]; bl[2 * np + 1][1] = r[3];
            }
#pragma unroll
            for (int ni = 0; ni < 8; ni++) MMA16816(acc[ni], ah, bh[ni]);
#pragma unroll
            for (int ni = 0; ni < 8; ni++) MMA16816(acc[ni], ah, bl[ni]);
#pragma unroll
            for (int ni = 0; ni < 8; ni++) MMA16816(acc[ni], al, bh[ni]);
        }
        __syncthreads();
    }

    {
        int qr = wq * 16 + (lane >> 2);
#pragma unroll
        for (int ni = 0; ni < 8; ni++) {
            int s = ws * 64 + ni * 8 + (lane & 3) * 2;
            float lw0 = c_lw[s >> 4] + c_lw[s & 15];
            float lw1 = c_lw[(s + 1) >> 4] + c_lw[(s + 1) & 15];
            sE[qr * 264 + s]           = acc[ni][0] + lw0;
            sE[qr * 264 + s + 1]       = acc[ni][1] + lw1;
            sE[(qr + 8) * 264 + s]     = acc[ni][2] + lw0;
            sE[(qr + 8) * 264 + s + 1] = acc[ni][3] + lw1;
        }
    }
    __syncthreads();

    // softmax + P fp16 single (each warp owns 4 rows)
    {
        hf* Pf = (hf*)(asmem + ATT_P);
        for (int r = wid * 4; r < wid * 4 + 4; r++) {
            float* row = sE + r * 264;
            float mx = -1e30f;
#pragma unroll
            for (int s = lane; s < 256; s += 32) mx = fmaxf(mx, row[s]);
#pragma unroll
            for (int o = 16; o > 0; o >>= 1) mx = fmaxf(mx, __shfl_xor_sync(0xffffffffu, mx, o));
            float sum = 0.f;
#pragma unroll
            for (int s = lane; s < 256; s += 32) {
                float e = __expf(row[s] - mx);
                row[s] = e;
                sum += e;
            }
#pragma unroll
            for (int o = 16; o > 0; o >>= 1) sum += __shfl_xor_sync(0xffffffffu, sum, o);
            float inv = 1.f / sum;
#pragma unroll
            for (int s = lane; s < 256; s += 32)
                Pf[r * 264 + s] = __float2half_rn(row[s] * inv);
        }
    }
    __syncthreads();

    // phase 2: O[32q][256hd] = P (single) x V (single), 1 product
    auto load_v = [&](int slot, int so) {
        const uint32_t st = sb + ATT_RING + slot * 40960;
        for (int i = tid; i < 1024; i += 256) {
            int r = i >> 2, sg = i & 3;
            cp_async16(st + r * 80 + sg * 16, vf_g + (size_t)r * NCOL + so + sg * 8);
        }
    };
    load_v(0, 0); cp_commit();

    float acc2[8][4];
#pragma unroll
    for (int ni = 0; ni < 8; ni++)
#pragma unroll
        for (int j = 0; j < 4; j++) acc2[ni][j] = 0.f;

    for (int ch = 0; ch < 8; ch++) {
        if (ch + 1 < 8) load_v((ch + 1) & 1, (ch + 1) * 32);
        cp_commit();
        cp_wait1();
        __syncthreads();
        const uint32_t st = sb + ATT_RING + (ch & 1) * 40960;
#pragma unroll
        for (int ks = 0; ks < 32; ks += 16) {
            uint32_t pf_[4];
            uint32_t paddr = sb + ATT_P + (wq * 16 + lrow) * 528 + (ch * 32 + ks + lcol) * 2;
            LDSM4(pf_, paddr);
            uint32_t b_[8][2];
#pragma unroll
            for (int np = 0; np < 4; np++) {
                uint32_t vaddr = st + (ws * 64 + np * 16 + lrow) * 80 + (ks + lcol) * 2;
                uint32_t r[4];
                LDSM4(r, vaddr);
                b_[2 * np][0] = r[0]; b_[2 * np][1] = r[2];
                b_[2 * np + 1][0] = r[1]; b_[2 * np + 1][1] = r[3];
            }
#pragma unroll
            for (int ni = 0; ni < 8; ni++) MMAH16816(acc2[ni], pf_, b_[ni]);
        }
        __syncthreads();
    }

    float* sO = sE;
    {
        int qloc = wq * 16 + (lane >> 2);
#pragma unroll
        for (int ni = 0; ni < 8; ni++) {
            int hd = ws * 64 + ni * 8 + (lane & 3) * 2;
            sO[hd * 33 + qloc]           = acc2[ni][0];
            sO[(hd + 1) * 33 + qloc]     = acc2[ni][1];
            sO[hd * 33 + qloc + 8]       = acc2[ni][2];
            sO[(hd + 1) * 33 + qloc + 8] = acc2[ni][3];
        }
    }
    __syncthreads();
    for (int i = tid; i < 8192; i += 256) {
        int r = i >> 5, q = i & 31;
        g_ao[(size_t)(n * 256 + r) * NCOL + b * 256 + q0 + q] = sO[r * 33 + q];
    }
}

// ---------------- combine: x1 = x + BN1(x) + gamma*ao ; BN2 -> transposed fp16 single ----------------
__global__ void combine_t_kernel(const float* __restrict__ x, const float* __restrict__ gamma,
                                 const float* __restrict__ g1, const float* __restrict__ b1p,
                                 const float* __restrict__ m1, const float* __restrict__ v1,
                                 const float* __restrict__ g2, const float* __restrict__ b2,
                                 const float* __restrict__ m2, const float* __restrict__ v2)
{
    __shared__ float t[32][33];
    int c0 = blockIdx.x * 32, col0 = blockIdx.y * 32;
    int tx = threadIdx.x, ty = threadIdx.y;
    int col = col0 + tx;
    int bb = col >> 8, hw = col & 255;
    float gm = gamma[0];
#pragma unroll
    for (int i = 0; i < 4; i++) {
        int c = c0 + ty + i * 8;
        size_t idx = (size_t)c * NCOL + col;
        float s1  = g1[c] * rsqrtf(v1[c] + EPSV);
        float sh1 = b1p[c] - m1[c] * s1;
        float xv  = x[((size_t)bb * CD + c) * HWD + hw];
        float x1  = xv + (xv * s1 + sh1) + gm * g_ao[idx];
        g_x1[idx] = x1;
        float s2 = g2[c] * rsqrtf(v2[c] + EPSV);
        t[ty + i * 8][tx] = x1 * s2 + (b2[c] - m2[c] * s2);
    }
    __syncthreads();
#pragma unroll
    for (int i = 0; i < 4; i++) {
        float val = t[tx][ty + i * 8];
        int n = col0 + ty + i * 8;
        g_x2f[(size_t)n * CD + c0 + tx] = __float2half_rn(val);
    }
}

// ---------------- launch ----------------
extern "C" void kernel_launch(void* const* d_in, const int* in_sizes, int n_in,
                              void* d_out, int out_size)
{
    const float* x     = (const float*)d_in[0];
    const float* bn1_g = (const float*)d_in[1];
    const float* bn1_b = (const float*)d_in[2];
    const float* bn1_m = (const float*)d_in[3];
    const float* bn1_v = (const float*)d_in[4];
    const float* Wq    = (const float*)d_in[5];
    const float* bq    = (const float*)d_in[6];
    const float* Wk    = (const float*)d_in[7];
    const float* bk    = (const float*)d_in[8];
    const float* Wv    = (const float*)d_in[9];
    const float* bv    = (const float*)d_in[10];
    const float* gamma = (const float*)d_in[11];
    const float* bn2_g = (const float*)d_in[12];
    const float* bn2_b = (const float*)d_in[13];
    const float* bn2_m = (const float*)d_in[14];
    const float* bn2_v = (const float*)d_in[15];
    const float* W1    = (const float*)d_in[16];
    const float* b1    = (const float*)d_in[17];
    const float* W2    = (const float*)d_in[18];
    const float* b2    = (const float*)d_in[19];
    float* out = (float*)d_out;

    hf *p_whf, *p_wlf, *p_wvf, *p_w1f, *p_w2f, *p_xf, *p_x2f, *p_hf;
    float *p_x1;
    cudaGetSymbolAddress((void**)&p_whf, g_whf);
    cudaGetSymbolAddress((void**)&p_wlf, g_wlf);
    cudaGetSymbolAddress((void**)&p_wvf, g_wvf);
    cudaGetSymbolAddress((void**)&p_w1f, g_w1f);
    cudaGetSymbolAddress((void**)&p_w2f, g_w2f);
    cudaGetSymbolAddress((void**)&p_xf,  g_xf);
    cudaGetSymbolAddress((void**)&p_x2f, g_x2f);
    cudaGetSymbolAddress((void**)&p_hf,  g_hf);
    cudaGetSymbolAddress((void**)&p_x1,  g_x1);

    constexpr int SMG2 = 2 * 3 * 64 * 80;   // 30720 (gemm2f_qk)
    constexpr int SMG1 = 2 * 2 * 64 * 80;   // 20480
    cudaFuncSetAttribute(gemm2f_qk,   cudaFuncAttributeMaxDynamicSharedMemorySize, SMG2);
    cudaFuncSetAttribute(gemm1_hf<0>, cudaFuncAttributeMaxDynamicSharedMemorySize, SMG1);
    cudaFuncSetAttribute(gemm1_hf<1>, cudaFuncAttributeMaxDynamicSharedMemorySize, SMG1);
    cudaFuncSetAttribute(gemm1_hf<2>, cudaFuncAttributeMaxDynamicSharedMemorySize, SMG1);
    cudaFuncSetAttribute(attn_kernel, cudaFuncAttributeMaxDynamicSharedMemorySize, ATT_SMEM);

    // weight splits + BN1
    wsplit_qk_kernel<<<dim3(1024, 2), 256>>>(Wq, Wk);
    wsplit_f_kernel<<<dim3(1024, 3), 256>>>(Wv, W1, W2);
    bn1_t_kernel<<<dim3(CD / 32, HWD / 32, 2), dim3(32, 8)>>>(x, bn1_g, bn1_b, bn1_m, bn1_v);

    // Q,K projection (fp16 2-product: W hi/lo x act single): M = 4096
    gemm2f_qk<<<dim3(64, 8), 128, SMG2>>>(p_whf, p_wlf, p_xf, bq, bk, CD);

    // V projection (fp16 1-product): M = 2048
    gemm1_hf<0><<<dim3(32, 8), 128, SMG1>>>(p_wvf, p_xf, bv, nullptr, nullptr, CD);

    // tensor-core attention
    attn_kernel<<<dim3(16, 8), 256, ATT_SMEM>>>();

    // residual + BN1-recompute + BN2 (-> fp16 single)
    combine_t_kernel<<<dim3(CD / 32, NCOL / 32), dim3(32, 8)>>>(
        x, gamma, bn1_g, bn1_b, bn1_m, bn1_v, bn2_g, bn2_b, bn2_m, bn2_v);

    // MLP1 (fp16 1-product): ReLU6 -> transposed fp16 single
    gemm1_hf<1><<<dim3(HID / 64, NCOL / 64), 128, SMG1>>>(p_w1f, p_x2f, b1, nullptr, nullptr, CD);

    // MLP2 (fp16 1-product): +residual, NCHW out
    gemm1_hf<2><<<dim3(CD / 64, NCOL / 64), 128, SMG1>>>(p_w2f, p_hf, b2, out, p_x1, HID);
}